// round 6
// baseline (speedup 1.0000x reference)
#include <cuda_runtime.h>
#include <cuda_bf16.h>

// Batched 1D linear interpolation with clamped extrapolation.
// t: [B, N] sorted per row, v: [B, N], r: [B, M]  ->  out: [B, M]
//
// One CTA per row, dynamic SMEM (112 KB, 2 CTAs/SM):
//   pair[i] = (t[i], v[i], t[i+1], v[i+1])  float4  -> final fetch is ONE
//             LDS.128 per query (was 4 scattered LDS.32 = the wavefront hog)
//   ts[i]   = t[i] packed float                     -> conflict-friendly probes
//   P[k]    = ushort bucket table, KB=16127 uniform buckets over [tmin,tmax]
//             (lambda ~= 0.25 knots/bucket), sentinel P[KB]=NN
// Refinement: 2 fixed branchless rounds (resolve width <= 3, ~99.985% of
// queries) where resolved lanes park on ts[0] (broadcast), plus a rare
// warp-voted fallback loop correct for ANY sorted t.

#define NN 4096
#define MM 4096
#define KB 16127
#define TABLE (KB + 1)               // even; P[KB] = NN sentinel
#define THREADS 512
#define QPT (MM / THREADS)           // 8 queries per thread

#define OFF_PAIRS 0
#define OFF_TS    (NN * 16)                    // 65536
#define OFF_P     (OFF_TS + NN * 4)            // 81920
#define SMEM_BYTES (OFF_P + TABLE * 2)         // 114176

__device__ __forceinline__ int bucket_of(float x, float tmin, float scale) {
    int k = (int)((x - tmin) * scale);   // monotone nondecreasing in x
    k = (k < 0) ? 0 : k;
    k = (k > KB - 1) ? KB - 1 : k;
    return k;
}

__global__ __launch_bounds__(THREADS, 2)
void interp1d_kernel(const float* __restrict__ t,
                     const float* __restrict__ v,
                     const float* __restrict__ r,
                     float* __restrict__ out) {
    extern __shared__ char smem[];
    float4*         pairs = reinterpret_cast<float4*>(smem + OFF_PAIRS);
    float*          ts    = reinterpret_cast<float*>(smem + OFF_TS);
    unsigned short* P     = reinterpret_cast<unsigned short*>(smem + OFF_P);

    const int row = blockIdx.x;
    const float* trow = t + (size_t)row * NN;
    const float* vrow = v + (size_t)row * NN;
    const float* rrow = r + (size_t)row * MM;
    float*       orow = out + (size_t)row * MM;
    const int tid = threadIdx.x;

    // ---- Stage knots: ts[] packed + pair[] gather-once layout ----
    const float4* t4 = reinterpret_cast<const float4*>(trow);
    const float4* v4 = reinterpret_cast<const float4*>(vrow);
    float4* ts4 = reinterpret_cast<float4*>(ts);
    #pragma unroll
    for (int i = 0; i < NN / 4 / THREADS; i++) {       // 2 iterations
        int i4 = tid + i * THREADS;
        int base = i4 * 4;
        float4 a = t4[i4];
        float4 b = v4[i4];
        float tn, vn;
        if (base + 4 < NN) { tn = trow[base + 4]; vn = vrow[base + 4]; }
        else               { tn = a.w;            vn = b.w; }
        pairs[base + 0] = make_float4(a.x, b.x, a.y, b.y);
        pairs[base + 1] = make_float4(a.y, b.y, a.z, b.z);
        pairs[base + 2] = make_float4(a.z, b.z, a.w, b.w);
        pairs[base + 3] = make_float4(a.w, b.w, tn, vn);
        ts4[i4] = a;
    }
    // ---- Init table to NN via u32 stores ----
    unsigned int* P32 = reinterpret_cast<unsigned int*>(P);
    const unsigned int fill = ((unsigned)NN << 16) | (unsigned)NN;
    #pragma unroll
    for (int i = 0; i < (TABLE / 2 + THREADS - 1) / THREADS; i++) {
        int j = tid + i * THREADS;
        if (j < TABLE / 2) P32[j] = fill;
    }
    __syncthreads();

    const float tmin   = ts[0];
    const float tmax   = ts[NN - 1];
    const float vfirst = pairs[0].y;
    const float vlast  = pairs[NN - 2].w;
    const float span   = tmax - tmin;
    const float scale  = (span > 0.0f) ? (float)KB / span : 0.0f;

    // ---- Build: knot j owns table range (bucket(t[j-1]), bucket(t[j])] ----
    #pragma unroll
    for (int i = 0; i < NN / THREADS; i++) {           // 8 iterations
        int j = tid + i * THREADS;
        int bj = bucket_of(ts[j], tmin, scale);
        int bp = (j == 0) ? -1 : bucket_of(ts[j - 1], tmin, scale);
        for (int k = bp + 1; k <= bj; k++) P[k] = (unsigned short)j;
    }
    __syncthreads();

    // ---- Queries: 8 per thread, 4 register-interleaved at a time ----
    #pragma unroll
    for (int b = 0; b < QPT / 4; b++) {
        float rv[4];
        #pragma unroll
        for (int q = 0; q < 4; q++)
            rv[q] = rrow[tid + (b * 4 + q) * THREADS];  // coalesced

        int lo[4], hi[4];
        #pragma unroll
        for (int q = 0; q < 4; q++) {
            int k = bucket_of(rv[q], tmin, scale);
            lo[q] = P[k];
            hi[q] = P[k + 1];                            // sentinel-safe
        }

        // 2 fixed branchless rounds; resolved lanes park on ts[0] (broadcast)
        #pragma unroll
        for (int rnd = 0; rnd < 2; rnd++) {
            #pragma unroll
            for (int q = 0; q < 4; q++) {
                bool go  = lo[q] < hi[q];
                int mid  = (lo[q] + hi[q]) >> 1;
                int addr = go ? mid : 0;                 // broadcast when done
                float tm = ts[addr];
                bool le  = tm <= rv[q];
                lo[q] = (go &&  le) ? mid + 1 : lo[q];
                hi[q] = (go && !le) ? mid     : hi[q];
            }
        }

        // rare fallback for width > 3 (correct for any sorted t)
        int rem = (hi[0] - lo[0]) | (hi[1] - lo[1]) |
                  (hi[2] - lo[2]) | (hi[3] - lo[3]);
        while (__any_sync(0xffffffffu, rem != 0)) {
            #pragma unroll
            for (int q = 0; q < 4; q++) {
                bool go  = lo[q] < hi[q];
                int mid  = (lo[q] + hi[q]) >> 1;
                int addr = go ? mid : 0;
                float tm = ts[addr];
                bool le  = tm <= rv[q];
                lo[q] = (go &&  le) ? mid + 1 : lo[q];
                hi[q] = (go && !le) ? mid     : hi[q];
            }
            rem = (hi[0] - lo[0]) | (hi[1] - lo[1]) |
                  (hi[2] - lo[2]) | (hi[3] - lo[3]);
        }

        float res[4];
        #pragma unroll
        for (int q = 0; q < 4; q++) {
            int idx = lo[q];
            idx = (idx < 1) ? 1 : idx;
            idx = (idx > NN - 1) ? NN - 1 : idx;
            float4 pp = pairs[idx - 1];                  // (t0, v0, t1, v1)
            float d = pp.z - pp.x;
            float denom = (d == 0.0f) ? 1.0f : d;
            float o = fmaf(rv[q] - pp.x, __fdividef(pp.w - pp.y, denom), pp.y);
            o = (rv[q] < tmin) ? vfirst : o;             // clamped extrapolation
            o = (rv[q] > tmax) ? vlast  : o;
            res[q] = o;
        }

        #pragma unroll
        for (int q = 0; q < 4; q++)
            orow[tid + (b * 4 + q) * THREADS] = res[q];
    }
}

extern "C" void kernel_launch(void* const* d_in, const int* in_sizes, int n_in,
                              void* d_out, int out_size) {
    const float* t = (const float*)d_in[0];
    const float* v = (const float*)d_in[1];
    const float* r = (const float*)d_in[2];
    float* out = (float*)d_out;

    cudaFuncSetAttribute(interp1d_kernel,
                         cudaFuncAttributeMaxDynamicSharedMemorySize, SMEM_BYTES);

    int B = in_sizes[0] / NN;   // 2048 for the reference shape
    interp1d_kernel<<<B, THREADS, SMEM_BYTES>>>(t, v, r, out);
}

// round 7
// speedup vs baseline: 1.5403x; 1.5403x over previous
#include <cuda_runtime.h>
#include <cuda_bf16.h>

// Batched 1D linear interpolation with clamped extrapolation.
// t: [B, N] sorted per row, v: [B, N], r: [B, M]  ->  out: [B, M]
//
// One CTA per row, 64KB dynamic SMEM (3 CTAs/SM):
//   ts[i] = t[i]          (packed f32: conflict-friendly random probes)
//   vs[i] = v[i]
//   sa[i] = slope of segment [i, i+1]  (precomputed: no division per query)
//   P[k]  = ushort bucket table, KB uniform buckets over [tmin,tmax],
//           sentinel P[KB] = NN
// Query: bucket -> [P[k], P[k+1]] -> 3 fixed branchless probe rounds
// (resolved lanes park on ts[0] broadcast) -> rare warp-voted fallback
// (correct for ANY sorted t) -> out = fmaf(r - t0, s, v0), 3 random LDS.32.

#define NN 4096
#define MM 4096
#define KB 8063
#define TABLE (KB + 1)               // even; P[KB] = NN sentinel
#define THREADS 512
#define QPT (MM / THREADS)           // 8 queries per thread

#define OFF_TS 0
#define OFF_VS (NN * 4)                    // 16384
#define OFF_SA (NN * 8)                    // 32768
#define OFF_P  (NN * 12)                   // 49152
#define SMEM_BYTES (OFF_P + TABLE * 2)     // 65280

__global__ __launch_bounds__(THREADS, 3)
void interp1d_kernel(const float* __restrict__ t,
                     const float* __restrict__ v,
                     const float* __restrict__ r,
                     float* __restrict__ out) {
    extern __shared__ char smem[];
    float*          ts = reinterpret_cast<float*>(smem + OFF_TS);
    float*          vs = reinterpret_cast<float*>(smem + OFF_VS);
    float*          sa = reinterpret_cast<float*>(smem + OFF_SA);
    unsigned short* P  = reinterpret_cast<unsigned short*>(smem + OFF_P);

    const int row = blockIdx.x;
    const float* trow = t + (size_t)row * NN;
    const float* vrow = v + (size_t)row * NN;
    const float* rrow = r + (size_t)row * MM;
    float*       orow = out + (size_t)row * MM;
    const int tid = threadIdx.x;

    // ---- Stage knots (float4 LDG -> STS.128) ----
    const float4* t4 = reinterpret_cast<const float4*>(trow);
    const float4* v4 = reinterpret_cast<const float4*>(vrow);
    float4* ts4 = reinterpret_cast<float4*>(ts);
    float4* vs4 = reinterpret_cast<float4*>(vs);
    #pragma unroll
    for (int i = 0; i < NN / 4 / THREADS; i++) {       // 2 iterations
        int i4 = tid + i * THREADS;
        ts4[i4] = t4[i4];
        vs4[i4] = v4[i4];
    }
    // ---- Init table to NN via u32 stores ----
    unsigned int* P32 = reinterpret_cast<unsigned int*>(P);
    const unsigned int fill = ((unsigned)NN << 16) | (unsigned)NN;
    #pragma unroll
    for (int i = 0; i < (TABLE / 2 + THREADS - 1) / THREADS; i++) {
        int j = tid + i * THREADS;
        if (j < TABLE / 2) P32[j] = fill;
    }
    __syncthreads();

    const float tmin   = ts[0];
    const float tmax   = ts[NN - 1];
    const float vfirst = vs[0];
    const float vlast  = vs[NN - 1];
    const float span   = tmax - tmin;
    const float scale  = (span > 0.0f) ? (float)KB / span : 0.0f;
    const float bias   = -tmin * scale;

    // bucket index: monotone in x, identical formula in build & query
    auto bucket_of = [&](float x) -> int {
        int k = (int)fmaf(x, scale, bias);
        k = (k < 0) ? 0 : k;
        k = (k > KB - 1) ? KB - 1 : k;
        return k;
    };

    // ---- Build slopes + bucket table ----
    #pragma unroll
    for (int i = 0; i < NN / THREADS; i++) {           // 8 iterations
        int j  = tid + i * THREADS;
        int jn = (j < NN - 1) ? j + 1 : j;
        float t0 = ts[j], t1 = ts[jn];
        float v0 = vs[j], v1 = vs[jn];
        float d = t1 - t0;
        float denom = (d == 0.0f) ? 1.0f : d;
        sa[j] = __fdividef(v1 - v0, denom);

        int bj = bucket_of(t0);
        int bp = (j == 0) ? -1 : bucket_of(ts[j - 1]);
        for (int k = bp + 1; k <= bj; k++) P[k] = (unsigned short)j;
    }
    __syncthreads();

    // ---- Queries: 8 per thread, 4 at a time (float4 I/O) ----
    const float4* r4 = reinterpret_cast<const float4*>(rrow);
    float4*       o4 = reinterpret_cast<float4*>(orow);

    #pragma unroll
    for (int b = 0; b < QPT / 4; b++) {
        float4 rq = r4[tid + b * THREADS];             // 1 LDG.128, coalesced
        float rv[4] = {rq.x, rq.y, rq.z, rq.w};

        int lo[4], hi[4];
        #pragma unroll
        for (int q = 0; q < 4; q++) {
            int k = bucket_of(rv[q]);
            lo[q] = P[k];
            hi[q] = P[k + 1];                          // sentinel-safe
        }

        // 3 fixed branchless rounds; resolved lanes park on ts[0] (broadcast)
        #pragma unroll
        for (int rnd = 0; rnd < 3; rnd++) {
            #pragma unroll
            for (int q = 0; q < 4; q++) {
                bool go  = lo[q] < hi[q];
                int mid  = (lo[q] + hi[q]) >> 1;
                int addr = go ? mid : 0;
                float tm = ts[addr];
                bool le  = tm <= rv[q];
                lo[q] = (go &&  le) ? mid + 1 : lo[q];
                hi[q] = (go && !le) ? mid     : hi[q];
            }
        }

        // rare fallback for width > 7 (correct for any sorted t)
        int rem = (hi[0] - lo[0]) | (hi[1] - lo[1]) |
                  (hi[2] - lo[2]) | (hi[3] - lo[3]);
        while (__any_sync(0xffffffffu, rem != 0)) {
            #pragma unroll
            for (int q = 0; q < 4; q++) {
                bool go  = lo[q] < hi[q];
                int mid  = (lo[q] + hi[q]) >> 1;
                int addr = go ? mid : 0;
                float tm = ts[addr];
                bool le  = tm <= rv[q];
                lo[q] = (go &&  le) ? mid + 1 : lo[q];
                hi[q] = (go && !le) ? mid     : hi[q];
            }
            rem = (hi[0] - lo[0]) | (hi[1] - lo[1]) |
                  (hi[2] - lo[2]) | (hi[3] - lo[3]);
        }

        float res[4];
        #pragma unroll
        for (int q = 0; q < 4; q++) {
            int idx = lo[q];
            idx = (idx < 1) ? 1 : idx;
            idx = (idx > NN - 1) ? NN - 1 : idx;
            float t0 = ts[idx - 1];                    // 3 random LDS.32
            float v0 = vs[idx - 1];
            float s  = sa[idx - 1];
            float o  = fmaf(rv[q] - t0, s, v0);
            o = (rv[q] < tmin) ? vfirst : o;           // clamped extrapolation
            o = (rv[q] > tmax) ? vlast  : o;
            res[q] = o;
        }

        o4[tid + b * THREADS] = make_float4(res[0], res[1], res[2], res[3]);
    }
}

extern "C" void kernel_launch(void* const* d_in, const int* in_sizes, int n_in,
                              void* d_out, int out_size) {
    const float* t = (const float*)d_in[0];
    const float* v = (const float*)d_in[1];
    const float* r = (const float*)d_in[2];
    float* out = (float*)d_out;

    cudaFuncSetAttribute(interp1d_kernel,
                         cudaFuncAttributeMaxDynamicSharedMemorySize, SMEM_BYTES);

    int B = in_sizes[0] / NN;   // 2048 for the reference shape
    interp1d_kernel<<<B, THREADS, SMEM_BYTES>>>(t, v, r, out);
}

// round 8
// speedup vs baseline: 1.5474x; 1.0046x over previous
#include <cuda_runtime.h>
#include <cuda_bf16.h>

// Batched 1D linear interpolation with clamped extrapolation.
// t: [B, N] sorted per row, v: [B, N], r: [B, M]  ->  out: [B, M]
//
// One CTA per row, 64KB dynamic SMEM (3 CTAs/SM):
//   ts[i] = t[i], vs[i] = v[i], sa[i] = slope of segment [i,i+1]
//   P[k]  = ushort bucket table over [tmin,tmax], sentinel P[KB]=NN.
//
// FUSED PROLOGUE: tmin/tmax come from uniform LDGs, so staging, slope
// computation, and the bucket-table scatter all happen in ONE pass over
// registers (neighbors via warp shuffle); the scatter ranges provably tile
// [0, KB-1], so there is no table-fill pass. One __syncthreads total.
//
// Query: bucket -> [P[k], P[k+1]] -> 2 fixed branchless probe rounds
// (resolved lanes park on ts[0] broadcast) + warp-voted fallback loop
// (correct for ANY sorted t) -> out = fmaf(r - t0, s, v0).

#define NN 4096
#define MM 4096
#define KB 8063
#define TABLE (KB + 1)               // P[KB] = NN sentinel
#define THREADS 512
#define QPT (MM / THREADS)           // 8 queries per thread

#define OFF_TS 0
#define OFF_VS (NN * 4)                    // 16384
#define OFF_SA (NN * 8)                    // 32768
#define OFF_P  (NN * 12)                   // 49152
#define SMEM_BYTES (OFF_P + TABLE * 2)     // 65280

__device__ __forceinline__ float seg_slope(float t0, float t1, float v0, float v1) {
    float d = t1 - t0;
    float denom = (d == 0.0f) ? 1.0f : d;
    return __fdividef(v1 - v0, denom);
}

__global__ __launch_bounds__(THREADS, 3)
void interp1d_kernel(const float* __restrict__ t,
                     const float* __restrict__ v,
                     const float* __restrict__ r,
                     float* __restrict__ out) {
    extern __shared__ char smem[];
    float*          ts = reinterpret_cast<float*>(smem + OFF_TS);
    float*          vs = reinterpret_cast<float*>(smem + OFF_VS);
    float*          sa = reinterpret_cast<float*>(smem + OFF_SA);
    unsigned short* P  = reinterpret_cast<unsigned short*>(smem + OFF_P);

    const int row = blockIdx.x;
    const float* trow = t + (size_t)row * NN;
    const float* vrow = v + (size_t)row * NN;
    const float* rrow = r + (size_t)row * MM;
    float*       orow = out + (size_t)row * MM;
    const int tid  = threadIdx.x;
    const int lane = tid & 31;

    // Uniform scalar loads (same address across warp -> 1 wavefront, L1/L2 hit)
    const float tmin   = trow[0];
    const float tmax   = trow[NN - 1];
    const float vfirst = vrow[0];
    const float vlast  = vrow[NN - 1];
    const float span   = tmax - tmin;
    const float scale  = (span > 0.0f) ? (float)KB / span : 0.0f;
    const float bias   = -tmin * scale;

    auto bucket_of = [&](float x) -> int {
        int k = (int)fmaf(x, scale, bias);   // monotone nondecreasing in x
        k = (k < 0) ? 0 : k;
        k = (k > KB - 1) ? KB - 1 : k;
        return k;
    };

    // ---- Fused staging + slopes + bucket-table scatter (register resident) ----
    const float4* t4 = reinterpret_cast<const float4*>(trow);
    const float4* v4 = reinterpret_cast<const float4*>(vrow);
    float4* ts4 = reinterpret_cast<float4*>(ts);
    float4* vs4 = reinterpret_cast<float4*>(vs);
    float4* sa4 = reinterpret_cast<float4*>(sa);

    #pragma unroll
    for (int i = 0; i < NN / 4 / THREADS; i++) {       // 2 iterations
        int i4   = tid + i * THREADS;
        int base = i4 * 4;
        float4 a = t4[i4];
        float4 b = v4[i4];
        ts4[i4] = a;
        vs4[i4] = b;

        // next element (t[base+4], v[base+4]) from lane+1; lane 31 via LDG
        float tn = __shfl_down_sync(0xffffffffu, a.x, 1);
        float vn = __shfl_down_sync(0xffffffffu, b.x, 1);
        if (lane == 31) {
            if (base + 4 < NN) { tn = trow[base + 4]; vn = vrow[base + 4]; }
            else               { tn = a.w;            vn = b.w; }
        }

        float4 s;
        s.x = seg_slope(a.x, a.y, b.x, b.y);
        s.y = seg_slope(a.y, a.z, b.y, b.z);
        s.z = seg_slope(a.z, a.w, b.z, b.w);
        s.w = seg_slope(a.w, tn,  b.w, vn);
        sa4[i4] = s;

        // previous element t[base-1] from lane-1; lane 0 via LDG
        float tp = __shfl_up_sync(0xffffffffu, a.w, 1);
        if (lane == 0 && base > 0) tp = trow[base - 1];
        int bprev = (base == 0) ? -1 : bucket_of(tp);
        int b0 = bucket_of(a.x);
        int b1 = bucket_of(a.y);
        int b2 = bucket_of(a.z);
        int b3 = bucket_of(a.w);
        for (int k = bprev + 1; k <= b0; k++) P[k] = (unsigned short)(base);
        for (int k = b0 + 1;    k <= b1; k++) P[k] = (unsigned short)(base + 1);
        for (int k = b1 + 1;    k <= b2; k++) P[k] = (unsigned short)(base + 2);
        for (int k = b2 + 1;    k <= b3; k++) P[k] = (unsigned short)(base + 3);
    }
    if (tid == 0) P[KB] = (unsigned short)NN;
    if (!(span > 0.0f)) {
        // degenerate row (all knots equal): never taken for real data, keeps
        // the table defined. Benign same-value race with the scatter above.
        for (int j = tid; j < KB; j += THREADS) P[j] = 0;
    }
    __syncthreads();

    // ---- Queries: 8 per thread, 4 register-interleaved at a time ----
    const float4* r4 = reinterpret_cast<const float4*>(rrow);
    float4*       o4 = reinterpret_cast<float4*>(orow);

    #pragma unroll
    for (int b = 0; b < QPT / 4; b++) {
        float4 rq = r4[tid + b * THREADS];             // 1 LDG.128, coalesced
        float rv[4] = {rq.x, rq.y, rq.z, rq.w};

        int lo[4], hi[4];
        #pragma unroll
        for (int q = 0; q < 4; q++) {
            int k = bucket_of(rv[q]);
            lo[q] = P[k];
            hi[q] = P[k + 1];                          // sentinel-safe
        }

        // 2 fixed branchless rounds; resolved lanes park on ts[0] (broadcast)
        #pragma unroll
        for (int rnd = 0; rnd < 2; rnd++) {
            #pragma unroll
            for (int q = 0; q < 4; q++) {
                bool go  = lo[q] < hi[q];
                int mid  = (lo[q] + hi[q]) >> 1;       // mid < hi <= NN, in range
                int addr = go ? mid : 0;
                float tm = ts[addr];
                bool le  = tm <= rv[q];
                lo[q] = (go &&  le) ? mid + 1 : lo[q];
                hi[q] = (go && !le) ? mid     : hi[q];
            }
        }

        // voted fallback (entered ~20% of batches; correct for any sorted t)
        int rem = (hi[0] - lo[0]) | (hi[1] - lo[1]) |
                  (hi[2] - lo[2]) | (hi[3] - lo[3]);
        while (__any_sync(0xffffffffu, rem != 0)) {
            #pragma unroll
            for (int q = 0; q < 4; q++) {
                bool go  = lo[q] < hi[q];
                int mid  = (lo[q] + hi[q]) >> 1;
                int addr = go ? mid : 0;
                float tm = ts[addr];
                bool le  = tm <= rv[q];
                lo[q] = (go &&  le) ? mid + 1 : lo[q];
                hi[q] = (go && !le) ? mid     : hi[q];
            }
            rem = (hi[0] - lo[0]) | (hi[1] - lo[1]) |
                  (hi[2] - lo[2]) | (hi[3] - lo[3]);
        }

        float res[4];
        #pragma unroll
        for (int q = 0; q < 4; q++) {
            int idx = lo[q];
            idx = (idx < 1) ? 1 : idx;
            idx = (idx > NN - 1) ? NN - 1 : idx;
            float t0 = ts[idx - 1];                    // 3 random LDS.32
            float v0 = vs[idx - 1];
            float s  = sa[idx - 1];
            float o  = fmaf(rv[q] - t0, s, v0);
            o = (rv[q] < tmin) ? vfirst : o;           // clamped extrapolation
            o = (rv[q] > tmax) ? vlast  : o;
            res[q] = o;
        }

        o4[tid + b * THREADS] = make_float4(res[0], res[1], res[2], res[3]);
    }
}

extern "C" void kernel_launch(void* const* d_in, const int* in_sizes, int n_in,
                              void* d_out, int out_size) {
    const float* t = (const float*)d_in[0];
    const float* v = (const float*)d_in[1];
    const float* r = (const float*)d_in[2];
    float* out = (float*)d_out;

    cudaFuncSetAttribute(interp1d_kernel,
                         cudaFuncAttributeMaxDynamicSharedMemorySize, SMEM_BYTES);

    int B = in_sizes[0] / NN;   // 2048 for the reference shape
    interp1d_kernel<<<B, THREADS, SMEM_BYTES>>>(t, v, r, out);
}